// round 1
// baseline (speedup 1.0000x reference)
#include <cuda_runtime.h>
#include <math.h>
#include <float.h>

// Problem constants (fixed shapes from reference)
#define BB 8192
#define DD 1024
#define NN 4096
#define LRC 0.02f
#define ATC 0.3f
#define ACOEF 0.002f    // LR * DSBETA
#define EPSDS 0.5f

// Scratch (device globals: no allocations allowed)
__device__ unsigned long long g_best[BB];   // packed (act_bits<<32) | (0xFFFFFFFF - n)
__device__ float g_x2[BB];
__device__ float g_w2[NN];
__device__ float g_rsum[NN];
__device__ float g_counts[NN];

// ---------------------------------------------------------------------------
// K0: zero scratch + sums region (d_out section 0) every launch (graph replay safe)
// ---------------------------------------------------------------------------
__global__ void k_init(float4* __restrict__ sums4) {
    int i = blockIdx.x * blockDim.x + threadIdx.x;   // grid covers NN*DD/4 exactly
    sums4[i] = make_float4(0.f, 0.f, 0.f, 0.f);
    if (i < BB) g_best[i] = 0ull;
    if (i < NN) g_counts[i] = 0.f;
}

// ---------------------------------------------------------------------------
// K1: row reductions: x2[b], w2[n], rsum[n]
// ---------------------------------------------------------------------------
__global__ void k_rowprep(const float* __restrict__ X,
                          const float* __restrict__ W,
                          const float* __restrict__ REL) {
    int r = blockIdx.x;
    int tid = threadIdx.x;   // 256 threads, 4 elems each (float4)
    __shared__ float s1[8], s2[8];
    float v1, v2 = 0.f;
    if (r < BB) {
        float4 v = ((const float4*)(X + (size_t)r * DD))[tid];
        v1 = v.x * v.x + v.y * v.y + v.z * v.z + v.w * v.w;
    } else {
        int n = r - BB;
        float4 wv = ((const float4*)(W + (size_t)n * DD))[tid];
        float4 rv = ((const float4*)(REL + (size_t)n * DD))[tid];
        v1 = wv.x * wv.x + wv.y * wv.y + wv.z * wv.z + wv.w * wv.w;
        v2 = rv.x + rv.y + rv.z + rv.w;
    }
#pragma unroll
    for (int o = 16; o > 0; o >>= 1) {
        v1 += __shfl_down_sync(0xFFFFFFFFu, v1, o);
        v2 += __shfl_down_sync(0xFFFFFFFFu, v2, o);
    }
    int w = tid >> 5, l = tid & 31;
    if (l == 0) { s1[w] = v1; s2[w] = v2; }
    __syncthreads();
    if (tid == 0) {
        float a = 0.f, b = 0.f;
#pragma unroll
        for (int i = 0; i < 8; i++) { a += s1[i]; b += s2[i]; }
        if (r < BB) g_x2[r] = a;
        else { g_w2[r - BB] = a; g_rsum[r - BB] = b; }
    }
}

// ---------------------------------------------------------------------------
// K2: fp32 GEMM (dot[b,n] = x_b . w_n) with fused activation + argmax epilogue
//     128x128 tile, BK=16, 256 threads, 8x8 per thread, double-buffered smem
// ---------------------------------------------------------------------------
__global__ void __launch_bounds__(256)
k_gemm_argmax(const float* __restrict__ X, const float* __restrict__ W,
              const float* __restrict__ NC) {
    __shared__ __align__(16) float As[2][16][128];
    __shared__ __align__(16) float Bs[2][16][128];

    const int tid = threadIdx.x;
    const int tx = tid & 15;     // 0..15 (n micro)
    const int ty = tid >> 4;     // 0..15 (b micro)
    const int lrow = tid >> 1;           // 0..127
    const int lcol = (tid & 1) * 8;      // 0 or 8

    const int bBase = blockIdx.y * 128;
    const int nBase = blockIdx.x * 128;

    const float* xg = X + (size_t)(bBase + lrow) * DD + lcol;
    const float* wg = W + (size_t)(nBase + lrow) * DD + lcol;

    // preload first k-tile
    float4 xa = *(const float4*)(xg);
    float4 xb = *(const float4*)(xg + 4);
    float4 wa = *(const float4*)(wg);
    float4 wb = *(const float4*)(wg + 4);

    As[0][lcol + 0][lrow] = xa.x; As[0][lcol + 1][lrow] = xa.y;
    As[0][lcol + 2][lrow] = xa.z; As[0][lcol + 3][lrow] = xa.w;
    As[0][lcol + 4][lrow] = xb.x; As[0][lcol + 5][lrow] = xb.y;
    As[0][lcol + 6][lrow] = xb.z; As[0][lcol + 7][lrow] = xb.w;
    Bs[0][lcol + 0][lrow] = wa.x; Bs[0][lcol + 1][lrow] = wa.y;
    Bs[0][lcol + 2][lrow] = wa.z; Bs[0][lcol + 3][lrow] = wa.w;
    Bs[0][lcol + 4][lrow] = wb.x; Bs[0][lcol + 5][lrow] = wb.y;
    Bs[0][lcol + 6][lrow] = wb.z; Bs[0][lcol + 7][lrow] = wb.w;
    __syncthreads();

    float acc[8][8];
#pragma unroll
    for (int i = 0; i < 8; i++)
#pragma unroll
        for (int j = 0; j < 8; j++) acc[i][j] = 0.f;

    const int NT = DD / 16;   // 64
    for (int t = 0; t < NT; t++) {
        const int cur = t & 1;
        if (t + 1 < NT) {
            const float* xg2 = xg + (t + 1) * 16;
            const float* wg2 = wg + (t + 1) * 16;
            xa = *(const float4*)(xg2);
            xb = *(const float4*)(xg2 + 4);
            wa = *(const float4*)(wg2);
            wb = *(const float4*)(wg2 + 4);
        }
#pragma unroll
        for (int k = 0; k < 16; k++) {
            float4 a0 = *(const float4*)&As[cur][k][ty * 8];
            float4 a1 = *(const float4*)&As[cur][k][ty * 8 + 4];
            float4 b0 = *(const float4*)&Bs[cur][k][tx * 4];
            float4 b1 = *(const float4*)&Bs[cur][k][64 + tx * 4];
            float ar[8] = {a0.x, a0.y, a0.z, a0.w, a1.x, a1.y, a1.z, a1.w};
            float br[8] = {b0.x, b0.y, b0.z, b0.w, b1.x, b1.y, b1.z, b1.w};
#pragma unroll
            for (int i = 0; i < 8; i++)
#pragma unroll
                for (int j = 0; j < 8; j++)
                    acc[i][j] = fmaf(ar[i], br[j], acc[i][j]);
        }
        if (t + 1 < NT) {
            const int nxt = cur ^ 1;
            As[nxt][lcol + 0][lrow] = xa.x; As[nxt][lcol + 1][lrow] = xa.y;
            As[nxt][lcol + 2][lrow] = xa.z; As[nxt][lcol + 3][lrow] = xa.w;
            As[nxt][lcol + 4][lrow] = xb.x; As[nxt][lcol + 5][lrow] = xb.y;
            As[nxt][lcol + 6][lrow] = xb.z; As[nxt][lcol + 7][lrow] = xb.w;
            Bs[nxt][lcol + 0][lrow] = wa.x; Bs[nxt][lcol + 1][lrow] = wa.y;
            Bs[nxt][lcol + 2][lrow] = wa.z; Bs[nxt][lcol + 3][lrow] = wa.w;
            Bs[nxt][lcol + 4][lrow] = wb.x; Bs[nxt][lcol + 5][lrow] = wb.y;
            Bs[nxt][lcol + 6][lrow] = wb.z; Bs[nxt][lcol + 7][lrow] = wb.w;
        }
        __syncthreads();
    }

    // ---- epilogue: act = rsum/(rsum + dist*(rsum/d) + 1e-7) * nc ; argmax ----
    int ncol[8];
    float rs[8], w2c[8], ncv[8], rsod[8];
#pragma unroll
    for (int j = 0; j < 8; j++) {
        int n = nBase + ((j < 4) ? (tx * 4 + j) : (64 + tx * 4 + (j - 4)));
        ncol[j] = n;
        rs[j] = g_rsum[n];
        w2c[j] = g_w2[n];
        ncv[j] = NC[n];
        rsod[j] = rs[j] * (1.0f / 1024.0f);
    }

    unsigned long long* red = (unsigned long long*)&As[0][0][0];  // 128 x 16 u64 = 16KB
#pragma unroll
    for (int i = 0; i < 8; i++) {
        int b = bBase + ty * 8 + i;
        float x2v = g_x2[b];
        unsigned long long key = 0ull;
#pragma unroll
        for (int j = 0; j < 8; j++) {
            float dist = (x2v + w2c[j]) - 2.0f * acc[i][j];
            float dw = dist * rsod[j];
            float den = (rs[j] + dw) + 1e-7f;
            float act = rs[j] / den * ncv[j];
            unsigned long long kk =
                ((unsigned long long)__float_as_uint(act) << 32) |
                (unsigned int)(0xFFFFFFFFu - (unsigned int)ncol[j]);
            key = (kk > key) ? kk : key;
        }
        red[(ty * 8 + i) * 16 + tx] = key;
    }
    __syncthreads();
    if (tid < 128) {
        unsigned long long m = red[tid * 16];
#pragma unroll
        for (int s = 1; s < 16; s++) {
            unsigned long long v = red[tid * 16 + s];
            m = (v > m) ? v : m;
        }
        atomicMax(&g_best[bBase + tid], m);
    }
}

// ---------------------------------------------------------------------------
// K3: scatter — segment sums via atomics (high mask is act_max >= AT)
// ---------------------------------------------------------------------------
__global__ void k_scatter(const float* __restrict__ X, float* __restrict__ sums) {
    int b = blockIdx.x;
    unsigned long long key = g_best[b];
    float act = __uint_as_float((unsigned int)(key >> 32));
    if (!(act >= ATC)) return;   // high = 0
    int n = (int)(0xFFFFFFFFu - (unsigned int)key);
    if (threadIdx.x == 0) atomicAdd(&g_counts[n], 1.0f);
    const float* xr = X + (size_t)b * DD;
    float* sr = sums + (size_t)n * DD;
#pragma unroll
    for (int k = 0; k < 4; k++) {
        int d = threadIdx.x + k * 256;
        atomicAdd(&sr[d], xr[d]);
    }
}

// ---------------------------------------------------------------------------
// K4: per-node finalize (mean_s, EMA moving_avg, row stats, relevance, weights)
// ---------------------------------------------------------------------------
__global__ void k_final(const float* __restrict__ W, const float* __restrict__ MAVG,
                        float* __restrict__ out) {
    int n = blockIdx.x;
    int tid = threadIdx.x;   // 256 threads x float4
    float cnt = g_counts[n];
    float has = (cnt > 0.f) ? 1.f : 0.f;
    float cmax = fmaxf(cnt, 1.f);

    float* out0 = out;
    float* out1 = out + (size_t)NN * DD;
    float* out2 = out + 2 * (size_t)NN * DD;

    float4 sv = ((const float4*)(out0 + (size_t)n * DD))[tid];   // sums (section 0)
    float4 wv = ((const float4*)(W + (size_t)n * DD))[tid];
    float4 av = ((const float4*)(MAVG + (size_t)n * DD))[tid];

    float mean[4] = {sv.x / cmax, sv.y / cmax, sv.z / cmax, sv.w / cmax};
    float wr[4] = {wv.x, wv.y, wv.z, wv.w};
    float ma[4] = {av.x, av.y, av.z, av.w};
    float mvn[4];
    float lmax = -FLT_MAX, lmin = FLT_MAX, lsum = 0.f;
#pragma unroll
    for (int j = 0; j < 4; j++) {
        float dist = fabsf(mean[j] - wr[j]);
        mvn[j] = ACOEF * dist + (1.0f - ACOEF) * ma[j];
        lmax = fmaxf(lmax, mvn[j]);
        lmin = fminf(lmin, mvn[j]);
        lsum += mvn[j];
    }
#pragma unroll
    for (int o = 16; o > 0; o >>= 1) {
        lmax = fmaxf(lmax, __shfl_down_sync(0xFFFFFFFFu, lmax, o));
        lmin = fminf(lmin, __shfl_down_sync(0xFFFFFFFFu, lmin, o));
        lsum += __shfl_down_sync(0xFFFFFFFFu, lsum, o);
    }
    __shared__ float smx[8], smn[8], ssm[8];
    __shared__ float rmx, rmn, rsm;
    int w = tid >> 5, l = tid & 31;
    if (l == 0) { smx[w] = lmax; smn[w] = lmin; ssm[w] = lsum; }
    __syncthreads();
    if (tid == 0) {
        float a = -FLT_MAX, b = FLT_MAX, c = 0.f;
#pragma unroll
        for (int i = 0; i < 8; i++) {
            a = fmaxf(a, smx[i]); b = fminf(b, smn[i]); c += ssm[i];
        }
        rmx = a; rmn = b; rsm = c;
    }
    __syncthreads();
    float mx = rmx, mn = rmn;
    float avg = rsm * (1.0f / 1024.0f);
    float scale = EPSDS * (mx - mn);

    float4 o0, o1, o2;
    float r0[4], r1[4], r2[4];
#pragma unroll
    for (int j = 0; j < 4; j++) {
        float t = (mvn[j] - avg) / scale;
        float r = 1.0f / (1.0f + expf(t));
        if (r != r) r = 1.0f;                      // NaN -> 1
        r0[j] = mean[j] * has;
        r1[j] = (wr[j] + LRC * (mean[j] - wr[j])) * has;
        r2[j] = r * has;
    }
    o0 = make_float4(r0[0], r0[1], r0[2], r0[3]);
    o1 = make_float4(r1[0], r1[1], r1[2], r1[3]);
    o2 = make_float4(r2[0], r2[1], r2[2], r2[3]);
    ((float4*)(out0 + (size_t)n * DD))[tid] = o0;
    ((float4*)(out1 + (size_t)n * DD))[tid] = o1;
    ((float4*)(out2 + (size_t)n * DD))[tid] = o2;
}

// ---------------------------------------------------------------------------
extern "C" void kernel_launch(void* const* d_in, const int* in_sizes, int n_in,
                              void* d_out, int out_size) {
    const float* x    = (const float*)d_in[0];
    const float* wts  = (const float*)d_in[1];
    const float* rel  = (const float*)d_in[2];
    const float* mavg = (const float*)d_in[3];
    const float* nc   = (const float*)d_in[4];
    float* out = (float*)d_out;

    k_init<<<(NN * DD / 4) / 256, 256>>>((float4*)out);
    k_rowprep<<<BB + NN, 256>>>(x, wts, rel);
    dim3 g(NN / 128, BB / 128);
    k_gemm_argmax<<<g, 256>>>(x, wts, nc);
    k_scatter<<<BB, 256>>>(x, out);
    k_final<<<NN, 256>>>(wts, mavg, out);
}

// round 4
// speedup vs baseline: 3.1927x; 3.1927x over previous
#include <cuda_runtime.h>
#include <cuda_bf16.h>
#include <math.h>
#include <float.h>
#include <cstdint>

#define BB 8192
#define DD 1024
#define NN 4096
#define LRC 0.02f
#define ATC 0.3f
#define ACOEF 0.002f
#define EPSDS 0.5f
#define MARGIN 2e-3f

// ---------------- device scratch (module globals; no runtime allocs) --------
__device__ unsigned long long g_best[BB];
__device__ float g_x2[BB];
__device__ float g_w2[NN];
__device__ float g_rsum[NN];
__device__ float g_counts[NN];
__device__ __nv_bfloat16 g_xb[BB * DD];     // 16 MB
__device__ __nv_bfloat16 g_wb[NN * DD];     // 8 MB
__device__ float g_act[(size_t)BB * NN];    // 128 MB approx activations

__device__ __forceinline__ uint32_t smem_u32(const void* p) {
    uint32_t a;
    asm("{ .reg .u64 t; cvta.to.shared.u64 t, %1; cvt.u32.u64 %0, t; }" : "=r"(a) : "l"(p));
    return a;
}

#define LDSM4(r0, r1, r2, r3, addr) \
    asm volatile("ldmatrix.sync.aligned.m8n8.x4.shared.b16 {%0,%1,%2,%3}, [%4];" \
                 : "=r"(r0), "=r"(r1), "=r"(r2), "=r"(r3) : "r"(addr))
#define LDSM2(r0, r1, addr) \
    asm volatile("ldmatrix.sync.aligned.m8n8.x2.shared.b16 {%0,%1}, [%2];" \
                 : "=r"(r0), "=r"(r1) : "r"(addr))
#define MMA16816(c0, c1, c2, c3, a0, a1, a2, a3, b0, b1) \
    asm volatile("mma.sync.aligned.m16n8k16.row.col.f32.bf16.bf16.f32 " \
                 "{%0,%1,%2,%3}, {%4,%5,%6,%7}, {%8,%9}, {%0,%1,%2,%3};" \
                 : "+f"(c0), "+f"(c1), "+f"(c2), "+f"(c3) \
                 : "r"(a0), "r"(a1), "r"(a2), "r"(a3), "r"(b0), "r"(b1))

// ---------------------------------------------------------------------------
// K0: zero sums region of d_out + counts
// ---------------------------------------------------------------------------
__global__ void k_init(float4* __restrict__ sums4) {
    int i = blockIdx.x * blockDim.x + threadIdx.x;
    sums4[i] = make_float4(0.f, 0.f, 0.f, 0.f);
    if (i < NN) g_counts[i] = 0.f;
}

// ---------------------------------------------------------------------------
// K1: row reductions + bf16 conversion of X and W
// ---------------------------------------------------------------------------
__global__ void k_rowprep(const float* __restrict__ X,
                          const float* __restrict__ W,
                          const float* __restrict__ REL) {
    int r = blockIdx.x;
    int tid = threadIdx.x;   // 256 threads x float4
    __shared__ float s1[8], s2[8];
    float v1, v2 = 0.f;
    if (r < BB) {
        float4 v = ((const float4*)(X + (size_t)r * DD))[tid];
        v1 = v.x * v.x + v.y * v.y + v.z * v.z + v.w * v.w;
        __nv_bfloat162 p0 = __floats2bfloat162_rn(v.x, v.y);
        __nv_bfloat162 p1 = __floats2bfloat162_rn(v.z, v.w);
        uint2 pk = make_uint2(*(uint32_t*)&p0, *(uint32_t*)&p1);
        *(uint2*)(g_xb + (size_t)r * DD + tid * 4) = pk;
    } else {
        int n = r - BB;
        float4 wv = ((const float4*)(W + (size_t)n * DD))[tid];
        float4 rv = ((const float4*)(REL + (size_t)n * DD))[tid];
        v1 = wv.x * wv.x + wv.y * wv.y + wv.z * wv.z + wv.w * wv.w;
        v2 = rv.x + rv.y + rv.z + rv.w;
        __nv_bfloat162 p0 = __floats2bfloat162_rn(wv.x, wv.y);
        __nv_bfloat162 p1 = __floats2bfloat162_rn(wv.z, wv.w);
        uint2 pk = make_uint2(*(uint32_t*)&p0, *(uint32_t*)&p1);
        *(uint2*)(g_wb + (size_t)n * DD + tid * 4) = pk;
    }
#pragma unroll
    for (int o = 16; o > 0; o >>= 1) {
        v1 += __shfl_down_sync(0xFFFFFFFFu, v1, o);
        v2 += __shfl_down_sync(0xFFFFFFFFu, v2, o);
    }
    int w = tid >> 5, l = tid & 31;
    if (l == 0) { s1[w] = v1; s2[w] = v2; }
    __syncthreads();
    if (tid == 0) {
        float a = 0.f, b = 0.f;
#pragma unroll
        for (int i = 0; i < 8; i++) { a += s1[i]; b += s2[i]; }
        if (r < BB) g_x2[r] = a;
        else { g_w2[r - BB] = a; g_rsum[r - BB] = b; }
    }
}

// ---------------------------------------------------------------------------
// K2: bf16 mma.sync GEMM (128x128x32 tiles) + act epilogue -> g_act
//   A smem layout per buffer: [chunk16][128 rows][24 bf16 (48B, 16 used)]
// ---------------------------------------------------------------------------
__global__ void __launch_bounds__(256, 2)
k_gemm_bf16(const float* __restrict__ NC) {
    __shared__ __align__(128) char sm[49152];   // A: [0,24576) B: [24576,49152)
    const uint32_t sb = smem_u32(sm);

    const int tid = threadIdx.x;
    const int l = tid & 31, wid = tid >> 5;
    const int warp_m = wid >> 2, warp_n = wid & 3;
    const int mBase = blockIdx.y * 128;
    const int nBase = blockIdx.x * 128;

    // global staging: thread -> (row, 16-col half)
    const int row = tid >> 1, h = tid & 1;
    const __nv_bfloat16* xg = g_xb + (size_t)(mBase + row) * DD + h * 16;
    const __nv_bfloat16* wg = g_wb + (size_t)(nBase + row) * DD + h * 16;
    char* aSt = sm + h * 6144 + row * 48;
    char* bSt = sm + 24576 + h * 6144 + row * 48;

    // preload k-iter 0
    int4 xa = *(const int4*)xg, xb2 = *(const int4*)(xg + 8);
    int4 wa = *(const int4*)wg, wb2 = *(const int4*)(wg + 8);
    *(int4*)aSt = xa; *(int4*)(aSt + 16) = xb2;
    *(int4*)bSt = wa; *(int4*)(bSt + 16) = wb2;
    __syncthreads();

    float c[4][4][4];
#pragma unroll
    for (int i = 0; i < 4; i++)
#pragma unroll
        for (int j = 0; j < 4; j++)
#pragma unroll
            for (int k = 0; k < 4; k++) c[i][j][k] = 0.f;

    const uint32_t aAddr0 = sb + (warp_m * 64 + (l & 15)) * 48 + (l >> 4) * 16;
    const uint32_t bAddr0 = sb + 24576 + (warp_n * 32 + (l & 7)) * 48 + ((l >> 3) & 1) * 16;

    for (int kt = 0; kt < 32; kt++) {
        const int buf = kt & 1;
        if (kt + 1 < 32) {
            const __nv_bfloat16* xp = xg + (kt + 1) * 32;
            const __nv_bfloat16* wp = wg + (kt + 1) * 32;
            xa = *(const int4*)xp; xb2 = *(const int4*)(xp + 8);
            wa = *(const int4*)wp; wb2 = *(const int4*)(wp + 8);
        }
        const uint32_t aB = aAddr0 + buf * 12288;
        const uint32_t bB = bAddr0 + buf * 12288;
#pragma unroll
        for (int ch = 0; ch < 2; ch++) {
            uint32_t a[4][4], b[4][2];
#pragma unroll
            for (int mt = 0; mt < 4; mt++)
                LDSM4(a[mt][0], a[mt][1], a[mt][2], a[mt][3], aB + ch * 6144 + mt * 768);
#pragma unroll
            for (int nt = 0; nt < 4; nt++)
                LDSM2(b[nt][0], b[nt][1], bB + ch * 6144 + nt * 384);
#pragma unroll
            for (int mt = 0; mt < 4; mt++)
#pragma unroll
                for (int nt = 0; nt < 4; nt++)
                    MMA16816(c[mt][nt][0], c[mt][nt][1], c[mt][nt][2], c[mt][nt][3],
                             a[mt][0], a[mt][1], a[mt][2], a[mt][3],
                             b[nt][0], b[nt][1]);
        }
        if (kt + 1 < 32) {
            const int nb = (kt + 1) & 1;
            *(int4*)(aSt + nb * 12288) = xa;
            *(int4*)(aSt + nb * 12288 + 16) = xb2;
            *(int4*)(bSt + nb * 12288) = wa;
            *(int4*)(bSt + nb * 12288 + 16) = wb2;
        }
        __syncthreads();
    }

    // epilogue: act and store to g_act
    float rsv[8], w2v[8], ncv[8];
    const int n2 = 2 * (l & 3);
#pragma unroll
    for (int nt = 0; nt < 4; nt++)
#pragma unroll
        for (int e = 0; e < 2; e++) {
            int n = nBase + warp_n * 32 + nt * 8 + n2 + e;
            rsv[nt * 2 + e] = g_rsum[n];
            w2v[nt * 2 + e] = g_w2[n];
            ncv[nt * 2 + e] = NC[n];
        }
#pragma unroll
    for (int mt = 0; mt < 4; mt++) {
#pragma unroll
        for (int hf = 0; hf < 2; hf++) {
            int brow = mBase + warp_m * 64 + mt * 16 + (l >> 2) + hf * 8;
            float x2v = g_x2[brow];
            float* orow = g_act + (size_t)brow * NN;
#pragma unroll
            for (int nt = 0; nt < 4; nt++) {
                float act[2];
#pragma unroll
                for (int e = 0; e < 2; e++) {
                    int i = nt * 2 + e;
                    float dot = c[mt][nt][hf * 2 + e];
                    float rs = rsv[i];
                    float dist = (x2v + w2v[i]) - 2.0f * dot;
                    float dw = dist * (rs * (1.0f / 1024.0f));
                    act[e] = rs / ((rs + dw) + 1e-7f) * ncv[i];
                }
                int n0 = nBase + warp_n * 32 + nt * 8 + n2;
                *(float2*)(orow + n0) = make_float2(act[0], act[1]);
            }
        }
    }
}

// ---------------------------------------------------------------------------
// K3: per-sample exact argmax: approx max -> candidates -> fp32 rescore
// ---------------------------------------------------------------------------
__global__ void __launch_bounds__(128)
k_argmax(const float* __restrict__ X, const float* __restrict__ W,
         const float* __restrict__ NC) {
    const int b = blockIdx.x;
    const int tid = threadIdx.x;   // 128
    const float* arow = g_act + (size_t)b * NN;

    // pass 1: approx max
    float am = -FLT_MAX;
    for (int j = tid; j < NN; j += 128) am = fmaxf(am, arow[j]);
#pragma unroll
    for (int o = 16; o > 0; o >>= 1) am = fmaxf(am, __shfl_down_sync(0xFFFFFFFFu, am, o));
    __shared__ float swm[4];
    __shared__ float amaxsh;
    if ((tid & 31) == 0) swm[tid >> 5] = am;
    __syncthreads();
    if (tid == 0) amaxsh = fmaxf(fmaxf(swm[0], swm[1]), fmaxf(swm[2], swm[3]));
    __syncthreads();
    const float thr = amaxsh - MARGIN;

    // pass 2: candidates (row is in L1 now)
    __shared__ int cand[64];
    __shared__ int ncand;
    if (tid == 0) ncand = 0;
    __syncthreads();
    for (int j = tid; j < NN; j += 128)
        if (arow[j] >= thr) {
            int p = atomicAdd(&ncand, 1);
            if (p < 64) cand[p] = j;
        }
    __syncthreads();
    const int nc_ = min(ncand, 64);

    // rescore exactly
    const float4* x4 = (const float4*)(X + (size_t)b * DD);
    const float x2v = g_x2[b];
    __shared__ float sdot[4];
    __shared__ unsigned long long sbest;
    if (tid == 0) sbest = 0ull;
    __syncthreads();
    for (int ci = 0; ci < nc_; ci++) {
        int n = cand[ci];
        const float4* w4 = (const float4*)(W + (size_t)n * DD);
        float p = 0.f;
        for (int j = tid; j < 256; j += 128) {
            float4 a = x4[j], w = w4[j];
            p += a.x * w.x + a.y * w.y + a.z * w.z + a.w * w.w;
        }
#pragma unroll
        for (int o = 16; o > 0; o >>= 1) p += __shfl_down_sync(0xFFFFFFFFu, p, o);
        if ((tid & 31) == 0) sdot[tid >> 5] = p;
        __syncthreads();
        if (tid == 0) {
            float dot = sdot[0] + sdot[1] + sdot[2] + sdot[3];
            float rs = g_rsum[n];
            float dist = (x2v + g_w2[n]) - 2.0f * dot;
            float dw = dist * (rs * (1.0f / 1024.0f));
            float act = rs / ((rs + dw) + 1e-7f) * NC[n];
            unsigned long long kk =
                ((unsigned long long)__float_as_uint(act) << 32) |
                (unsigned int)(0xFFFFFFFFu - (unsigned int)n);
            if (kk > sbest) sbest = kk;
        }
        __syncthreads();
    }
    if (tid == 0) g_best[b] = sbest;
}

// ---------------------------------------------------------------------------
// K4: scatter — segment sums via atomics
// ---------------------------------------------------------------------------
__global__ void k_scatter(const float* __restrict__ X, float* __restrict__ sums) {
    int b = blockIdx.x;
    unsigned long long key = g_best[b];
    float act = __uint_as_float((unsigned int)(key >> 32));
    if (!(act >= ATC)) return;
    int n = (int)(0xFFFFFFFFu - (unsigned int)key);
    if (threadIdx.x == 0) atomicAdd(&g_counts[n], 1.0f);
    const float* xr = X + (size_t)b * DD;
    float* sr = sums + (size_t)n * DD;
#pragma unroll
    for (int k = 0; k < 4; k++) {
        int d = threadIdx.x + k * 256;
        atomicAdd(&sr[d], xr[d]);
    }
}

// ---------------------------------------------------------------------------
// K5: finalize
// ---------------------------------------------------------------------------
__global__ void k_final(const float* __restrict__ W, const float* __restrict__ MAVG,
                        float* __restrict__ out) {
    int n = blockIdx.x;
    int tid = threadIdx.x;
    float cnt = g_counts[n];
    float has = (cnt > 0.f) ? 1.f : 0.f;
    float cmax = fmaxf(cnt, 1.f);

    float* out0 = out;
    float* out1 = out + (size_t)NN * DD;
    float* out2 = out + 2 * (size_t)NN * DD;

    float4 sv = ((const float4*)(out0 + (size_t)n * DD))[tid];
    float4 wv = ((const float4*)(W + (size_t)n * DD))[tid];
    float4 av = ((const float4*)(MAVG + (size_t)n * DD))[tid];

    float mean[4] = {sv.x / cmax, sv.y / cmax, sv.z / cmax, sv.w / cmax};
    float wr[4] = {wv.x, wv.y, wv.z, wv.w};
    float ma[4] = {av.x, av.y, av.z, av.w};
    float mvn[4];
    float lmax = -FLT_MAX, lmin = FLT_MAX, lsum = 0.f;
#pragma unroll
    for (int j = 0; j < 4; j++) {
        float dist = fabsf(mean[j] - wr[j]);
        mvn[j] = ACOEF * dist + (1.0f - ACOEF) * ma[j];
        lmax = fmaxf(lmax, mvn[j]);
        lmin = fminf(lmin, mvn[j]);
        lsum += mvn[j];
    }
#pragma unroll
    for (int o = 16; o > 0; o >>= 1) {
        lmax = fmaxf(lmax, __shfl_down_sync(0xFFFFFFFFu, lmax, o));
        lmin = fminf(lmin, __shfl_down_sync(0xFFFFFFFFu, lmin, o));
        lsum += __shfl_down_sync(0xFFFFFFFFu, lsum, o);
    }
    __shared__ float smx[8], smn[8], ssm[8];
    __shared__ float rmx, rmn, rsm;
    int w = tid >> 5, l = tid & 31;
    if (l == 0) { smx[w] = lmax; smn[w] = lmin; ssm[w] = lsum; }
    __syncthreads();
    if (tid == 0) {
        float a = -FLT_MAX, b2 = FLT_MAX, cc = 0.f;
#pragma unroll
        for (int i = 0; i < 8; i++) {
            a = fmaxf(a, smx[i]); b2 = fminf(b2, smn[i]); cc += ssm[i];
        }
        rmx = a; rmn = b2; rsm = cc;
    }
    __syncthreads();
    float avg = rsm * (1.0f / 1024.0f);
    float scale = EPSDS * (rmx - rmn);

    float r0[4], r1[4], r2[4];
#pragma unroll
    for (int j = 0; j < 4; j++) {
        float t = (mvn[j] - avg) / scale;
        float r = 1.0f / (1.0f + expf(t));
        if (r != r) r = 1.0f;
        r0[j] = mean[j] * has;
        r1[j] = (wr[j] + LRC * (mean[j] - wr[j])) * has;
        r2[j] = r * has;
    }
    ((float4*)(out0 + (size_t)n * DD))[tid] = make_float4(r0[0], r0[1], r0[2], r0[3]);
    ((float4*)(out1 + (size_t)n * DD))[tid] = make_float4(r1[0], r1[1], r1[2], r1[3]);
    ((float4*)(out2 + (size_t)n * DD))[tid] = make_float4(r2[0], r2[1], r2[2], r2[3]);
}

// ---------------------------------------------------------------------------
extern "C" void kernel_launch(void* const* d_in, const int* in_sizes, int n_in,
                              void* d_out, int out_size) {
    const float* x    = (const float*)d_in[0];
    const float* wts  = (const float*)d_in[1];
    const float* rel  = (const float*)d_in[2];
    const float* mavg = (const float*)d_in[3];
    const float* nc   = (const float*)d_in[4];
    float* out = (float*)d_out;

    k_init<<<(NN * DD / 4) / 256, 256>>>((float4*)out);
    k_rowprep<<<BB + NN, 256>>>(x, wts, rel);
    dim3 g(NN / 128, BB / 128);
    k_gemm_bf16<<<g, 256>>>(nc);
    k_argmax<<<BB, 128>>>(x, wts, nc);
    k_scatter<<<BB, 256>>>(x, out);
    k_final<<<NN, 256>>>(wts, mavg, out);
}

// round 5
// speedup vs baseline: 3.2784x; 1.0268x over previous
#include <cuda_runtime.h>
#include <cuda_bf16.h>
#include <math.h>
#include <float.h>
#include <cstdint>

#define BB 8192
#define DD 1024
#define NN 4096
#define LRC 0.02f
#define ATC 0.3f
#define ACOEF 0.002f
#define EPSDS 0.5f
#define MARGIN 4e-3f

// ---------------- device scratch ----------------
__device__ unsigned long long g_best[BB];
__device__ float g_x2[BB];
__device__ float g_w2[NN];
__device__ float g_rsum[NN];
__device__ float g_counts[NN];
__device__ unsigned int g_rowmax[BB];        // f32 bits (acts > 0)
__device__ __nv_bfloat16 g_xb[BB * DD];      // 16 MB
__device__ __nv_bfloat16 g_wb[NN * DD];      // 8 MB
__device__ __nv_bfloat16 g_actb[(size_t)BB * NN];  // 64 MB approx acts (bf16)

__device__ __forceinline__ uint32_t smem_u32(const void* p) {
    uint32_t a;
    asm("{ .reg .u64 t; cvta.to.shared.u64 t, %1; cvt.u32.u64 %0, t; }" : "=r"(a) : "l"(p));
    return a;
}

#define LDSM4(r0, r1, r2, r3, addr) \
    asm volatile("ldmatrix.sync.aligned.m8n8.x4.shared.b16 {%0,%1,%2,%3}, [%4];" \
                 : "=r"(r0), "=r"(r1), "=r"(r2), "=r"(r3) : "r"(addr))
#define LDSM2(r0, r1, addr) \
    asm volatile("ldmatrix.sync.aligned.m8n8.x2.shared.b16 {%0,%1}, [%2];" \
                 : "=r"(r0), "=r"(r1) : "r"(addr))
#define MMA16816(c0, c1, c2, c3, a0, a1, a2, a3, b0, b1) \
    asm volatile("mma.sync.aligned.m16n8k16.row.col.f32.bf16.bf16.f32 " \
                 "{%0,%1,%2,%3}, {%4,%5,%6,%7}, {%8,%9}, {%0,%1,%2,%3};" \
                 : "+f"(c0), "+f"(c1), "+f"(c2), "+f"(c3) \
                 : "r"(a0), "r"(a1), "r"(a2), "r"(a3), "r"(b0), "r"(b1))
#define CPASYNC16(dst, src) \
    asm volatile("cp.async.ca.shared.global [%0], [%1], 16;" :: "r"(dst), "l"(src))
#define CPCOMMIT() asm volatile("cp.async.commit_group;" ::: "memory")
#define CPWAIT1() asm volatile("cp.async.wait_group 1;" ::: "memory")

// stage layout: stage s at s*24576; A chunk h at +h*6144 (row*48); B at +12288+h*6144
static constexpr int STAGE_B = 24576;
static constexpr int GEMM_SMEM = 3 * STAGE_B;   // 73728

// ---------------------------------------------------------------------------
// K0: zero sums region + counts + rowmax
// ---------------------------------------------------------------------------
__global__ void k_init(float4* __restrict__ sums4) {
    int i = blockIdx.x * blockDim.x + threadIdx.x;
    sums4[i] = make_float4(0.f, 0.f, 0.f, 0.f);
    if (i < NN) g_counts[i] = 0.f;
    if (i < BB) g_rowmax[i] = 0u;
}

// ---------------------------------------------------------------------------
// K1: row reductions + bf16 conversion
// ---------------------------------------------------------------------------
__global__ void k_rowprep(const float* __restrict__ X,
                          const float* __restrict__ W,
                          const float* __restrict__ REL) {
    int r = blockIdx.x;
    int tid = threadIdx.x;
    __shared__ float s1[8], s2[8];
    float v1, v2 = 0.f;
    if (r < BB) {
        float4 v = ((const float4*)(X + (size_t)r * DD))[tid];
        v1 = v.x * v.x + v.y * v.y + v.z * v.z + v.w * v.w;
        __nv_bfloat162 p0 = __floats2bfloat162_rn(v.x, v.y);
        __nv_bfloat162 p1 = __floats2bfloat162_rn(v.z, v.w);
        uint2 pk = make_uint2(*(uint32_t*)&p0, *(uint32_t*)&p1);
        *(uint2*)(g_xb + (size_t)r * DD + tid * 4) = pk;
    } else {
        int n = r - BB;
        float4 wv = ((const float4*)(W + (size_t)n * DD))[tid];
        float4 rv = ((const float4*)(REL + (size_t)n * DD))[tid];
        v1 = wv.x * wv.x + wv.y * wv.y + wv.z * wv.z + wv.w * wv.w;
        v2 = rv.x + rv.y + rv.z + rv.w;
        __nv_bfloat162 p0 = __floats2bfloat162_rn(wv.x, wv.y);
        __nv_bfloat162 p1 = __floats2bfloat162_rn(wv.z, wv.w);
        uint2 pk = make_uint2(*(uint32_t*)&p0, *(uint32_t*)&p1);
        *(uint2*)(g_wb + (size_t)n * DD + tid * 4) = pk;
    }
#pragma unroll
    for (int o = 16; o > 0; o >>= 1) {
        v1 += __shfl_down_sync(0xFFFFFFFFu, v1, o);
        v2 += __shfl_down_sync(0xFFFFFFFFu, v2, o);
    }
    int w = tid >> 5, l = tid & 31;
    if (l == 0) { s1[w] = v1; s2[w] = v2; }
    __syncthreads();
    if (tid == 0) {
        float a = 0.f, b = 0.f;
#pragma unroll
        for (int i = 0; i < 8; i++) { a += s1[i]; b += s2[i]; }
        if (r < BB) g_x2[r] = a;
        else { g_w2[r - BB] = a; g_rsum[r - BB] = b; }
    }
}

// ---------------------------------------------------------------------------
// K2: bf16 mma.sync GEMM, cp.async 3-stage; epilogue -> bf16 acts + rowmax
// ---------------------------------------------------------------------------
__global__ void __launch_bounds__(256, 2)
k_gemm_bf16(const float* __restrict__ NC) {
    extern __shared__ __align__(128) char sm[];
    const uint32_t sb = smem_u32(sm);

    const int tid = threadIdx.x;
    const int l = tid & 31, wid = tid >> 5;
    const int warp_m = wid >> 2, warp_n = wid & 3;
    const int mBase = blockIdx.y * 128;
    const int nBase = blockIdx.x * 128;

    // load mapping: thread -> (row, 16-col half)
    const int row = tid >> 1, h = tid & 1;
    const __nv_bfloat16* xg = g_xb + (size_t)(mBase + row) * DD + h * 16;
    const __nv_bfloat16* wg = g_wb + (size_t)(nBase + row) * DD + h * 16;
    const uint32_t aDst = sb + h * 6144 + row * 48;
    const uint32_t bDst = sb + 12288 + h * 6144 + row * 48;

    // prologue: stages 0,1
#pragma unroll
    for (int s = 0; s < 2; s++) {
        const __nv_bfloat16* xs = xg + s * 32;
        const __nv_bfloat16* ws = wg + s * 32;
        CPASYNC16(aDst + s * STAGE_B, xs);
        CPASYNC16(aDst + s * STAGE_B + 16, xs + 8);
        CPASYNC16(bDst + s * STAGE_B, ws);
        CPASYNC16(bDst + s * STAGE_B + 16, ws + 8);
        CPCOMMIT();
    }

    float c[4][4][4];
#pragma unroll
    for (int i = 0; i < 4; i++)
#pragma unroll
        for (int j = 0; j < 4; j++)
#pragma unroll
            for (int k = 0; k < 4; k++) c[i][j][k] = 0.f;

    const uint32_t aAddr0 = sb + (warp_m * 64 + (l & 15)) * 48 + (l >> 4) * 16;
    const uint32_t bAddr0 = sb + 12288 + (warp_n * 32 + (l & 7)) * 48 + ((l >> 3) & 1) * 16;

    for (int kt = 0; kt < 32; kt++) {
        CPWAIT1();
        __syncthreads();
        // issue stage kt+2 (overwrites buffer last read at iter kt-1)
        if (kt + 2 < 32) {
            const int s = (kt + 2) % 3;
            const __nv_bfloat16* xs = xg + (kt + 2) * 32;
            const __nv_bfloat16* ws = wg + (kt + 2) * 32;
            CPASYNC16(aDst + s * STAGE_B, xs);
            CPASYNC16(aDst + s * STAGE_B + 16, xs + 8);
            CPASYNC16(bDst + s * STAGE_B, ws);
            CPASYNC16(bDst + s * STAGE_B + 16, ws + 8);
        }
        CPCOMMIT();   // always commit (possibly empty) to keep group count regular

        const uint32_t aB = aAddr0 + (kt % 3) * STAGE_B;
        const uint32_t bB = bAddr0 + (kt % 3) * STAGE_B;
#pragma unroll
        for (int ch = 0; ch < 2; ch++) {
            uint32_t a[4][4], b[4][2];
#pragma unroll
            for (int mt = 0; mt < 4; mt++)
                LDSM4(a[mt][0], a[mt][1], a[mt][2], a[mt][3], aB + ch * 6144 + mt * 768);
#pragma unroll
            for (int nt = 0; nt < 4; nt++)
                LDSM2(b[nt][0], b[nt][1], bB + ch * 6144 + nt * 384);
#pragma unroll
            for (int mt = 0; mt < 4; mt++)
#pragma unroll
                for (int nt = 0; nt < 4; nt++)
                    MMA16816(c[mt][nt][0], c[mt][nt][1], c[mt][nt][2], c[mt][nt][3],
                             a[mt][0], a[mt][1], a[mt][2], a[mt][3],
                             b[nt][0], b[nt][1]);
        }
        __syncthreads();
    }

    // ---- epilogue: act -> bf16 g_actb, per-row max -> g_rowmax ----
    float rsv[8], w2v[8], ncv[8];
    const int n2 = 2 * (l & 3);
#pragma unroll
    for (int nt = 0; nt < 4; nt++)
#pragma unroll
        for (int e = 0; e < 2; e++) {
            int n = nBase + warp_n * 32 + nt * 8 + n2 + e;
            rsv[nt * 2 + e] = g_rsum[n];
            w2v[nt * 2 + e] = g_w2[n];
            ncv[nt * 2 + e] = NC[n];
        }
#pragma unroll
    for (int mt = 0; mt < 4; mt++) {
#pragma unroll
        for (int hf = 0; hf < 2; hf++) {
            int brow = mBase + warp_m * 64 + mt * 16 + (l >> 2) + hf * 8;
            float x2v = g_x2[brow];
            __nv_bfloat16* orow = g_actb + (size_t)brow * NN;
            float rmax = 0.f;
#pragma unroll
            for (int nt = 0; nt < 4; nt++) {
                float act[2];
#pragma unroll
                for (int e = 0; e < 2; e++) {
                    int i = nt * 2 + e;
                    float dot = c[mt][nt][hf * 2 + e];
                    float rs = rsv[i];
                    float dist = (x2v + w2v[i]) - 2.0f * dot;
                    float dw = dist * (rs * (1.0f / 1024.0f));
                    act[e] = rs / ((rs + dw) + 1e-7f) * ncv[i];
                    rmax = fmaxf(rmax, act[e]);
                }
                int n0 = nBase + warp_n * 32 + nt * 8 + n2;
                __nv_bfloat162 pb = __floats2bfloat162_rn(act[0], act[1]);
                *(uint32_t*)(orow + n0) = *(uint32_t*)&pb;
            }
            // reduce max across the 4 lanes sharing this row (l&3 varies)
            rmax = fmaxf(rmax, __shfl_xor_sync(0xFFFFFFFFu, rmax, 1));
            rmax = fmaxf(rmax, __shfl_xor_sync(0xFFFFFFFFu, rmax, 2));
            if ((l & 3) == 0)
                atomicMax(&g_rowmax[brow], __float_as_uint(rmax));
        }
    }
}

// ---------------------------------------------------------------------------
// K3: single-pass candidate gather + exact fp32 rescore
// ---------------------------------------------------------------------------
__global__ void __launch_bounds__(256)
k_argmax(const float* __restrict__ X, const float* __restrict__ W,
         const float* __restrict__ NC) {
    const int b = blockIdx.x;
    const int tid = threadIdx.x;   // 256
    const float thr = __uint_as_float(g_rowmax[b]) - MARGIN;

    __shared__ int cand[64];
    __shared__ int ncand;
    if (tid == 0) ncand = 0;
    __syncthreads();

    const uint4* arow = (const uint4*)(g_actb + (size_t)b * NN);  // 512 uint4
#pragma unroll
    for (int it = 0; it < 2; it++) {
        int idx = tid + it * 256;
        uint4 v = arow[idx];
        uint32_t ws[4] = {v.x, v.y, v.z, v.w};
#pragma unroll
        for (int q = 0; q < 4; q++) {
            __nv_bfloat162 h2 = *(__nv_bfloat162*)&ws[q];
            float a0 = __low2float(h2), a1 = __high2float(h2);
            if (a0 >= thr) { int p = atomicAdd(&ncand, 1); if (p < 64) cand[p] = idx * 8 + q * 2; }
            if (a1 >= thr) { int p = atomicAdd(&ncand, 1); if (p < 64) cand[p] = idx * 8 + q * 2 + 1; }
        }
    }
    __syncthreads();
    const int nc_ = min(ncand, 64);

    const float4* x4 = (const float4*)(X + (size_t)b * DD);
    const float x2v = g_x2[b];
    __shared__ float sdot[8];
    __shared__ unsigned long long sbest;
    if (tid == 0) sbest = 0ull;
    __syncthreads();
    for (int ci = 0; ci < nc_; ci++) {
        int n = cand[ci];
        const float4* w4 = (const float4*)(W + (size_t)n * DD);
        float4 a = x4[tid], w = w4[tid];
        float p = a.x * w.x + a.y * w.y + a.z * w.z + a.w * w.w;
#pragma unroll
        for (int o = 16; o > 0; o >>= 1) p += __shfl_down_sync(0xFFFFFFFFu, p, o);
        if ((tid & 31) == 0) sdot[tid >> 5] = p;
        __syncthreads();
        if (tid == 0) {
            float dot = 0.f;
#pragma unroll
            for (int q = 0; q < 8; q++) dot += sdot[q];
            float rs = g_rsum[n];
            float dist = (x2v + g_w2[n]) - 2.0f * dot;
            float dw = dist * (rs * (1.0f / 1024.0f));
            float act = rs / ((rs + dw) + 1e-7f) * NC[n];
            unsigned long long kk =
                ((unsigned long long)__float_as_uint(act) << 32) |
                (unsigned int)(0xFFFFFFFFu - (unsigned int)n);
            if (kk > sbest) sbest = kk;
        }
        __syncthreads();
    }
    if (tid == 0) g_best[b] = sbest;
}

// ---------------------------------------------------------------------------
// K4: scatter
// ---------------------------------------------------------------------------
__global__ void k_scatter(const float* __restrict__ X, float* __restrict__ sums) {
    int b = blockIdx.x;
    unsigned long long key = g_best[b];
    float act = __uint_as_float((unsigned int)(key >> 32));
    if (!(act >= ATC)) return;
    int n = (int)(0xFFFFFFFFu - (unsigned int)key);
    if (threadIdx.x == 0) atomicAdd(&g_counts[n], 1.0f);
    const float* xr = X + (size_t)b * DD;
    float* sr = sums + (size_t)n * DD;
#pragma unroll
    for (int k = 0; k < 4; k++) {
        int d = threadIdx.x + k * 256;
        atomicAdd(&sr[d], xr[d]);
    }
}

// ---------------------------------------------------------------------------
// K5: finalize
// ---------------------------------------------------------------------------
__global__ void k_final(const float* __restrict__ W, const float* __restrict__ MAVG,
                        float* __restrict__ out) {
    int n = blockIdx.x;
    int tid = threadIdx.x;
    float cnt = g_counts[n];
    float has = (cnt > 0.f) ? 1.f : 0.f;
    float cmax = fmaxf(cnt, 1.f);

    float* out0 = out;
    float* out1 = out + (size_t)NN * DD;
    float* out2 = out + 2 * (size_t)NN * DD;

    float4 sv = ((const float4*)(out0 + (size_t)n * DD))[tid];
    float4 wv = ((const float4*)(W + (size_t)n * DD))[tid];
    float4 av = ((const float4*)(MAVG + (size_t)n * DD))[tid];

    float mean[4] = {sv.x / cmax, sv.y / cmax, sv.z / cmax, sv.w / cmax};
    float wr[4] = {wv.x, wv.y, wv.z, wv.w};
    float ma[4] = {av.x, av.y, av.z, av.w};
    float mvn[4];
    float lmax = -FLT_MAX, lmin = FLT_MAX, lsum = 0.f;
#pragma unroll
    for (int j = 0; j < 4; j++) {
        float dist = fabsf(mean[j] - wr[j]);
        mvn[j] = ACOEF * dist + (1.0f - ACOEF) * ma[j];
        lmax = fmaxf(lmax, mvn[j]);
        lmin = fminf(lmin, mvn[j]);
        lsum += mvn[j];
    }
#pragma unroll
    for (int o = 16; o > 0; o >>= 1) {
        lmax = fmaxf(lmax, __shfl_down_sync(0xFFFFFFFFu, lmax, o));
        lmin = fminf(lmin, __shfl_down_sync(0xFFFFFFFFu, lmin, o));
        lsum += __shfl_down_sync(0xFFFFFFFFu, lsum, o);
    }
    __shared__ float smx[8], smn[8], ssm[8];
    __shared__ float rmx, rmn, rsm;
    int w = tid >> 5, l = tid & 31;
    if (l == 0) { smx[w] = lmax; smn[w] = lmin; ssm[w] = lsum; }
    __syncthreads();
    if (tid == 0) {
        float a = -FLT_MAX, b2 = FLT_MAX, cc = 0.f;
#pragma unroll
        for (int i = 0; i < 8; i++) {
            a = fmaxf(a, smx[i]); b2 = fminf(b2, smn[i]); cc += ssm[i];
        }
        rmx = a; rmn = b2; rsm = cc;
    }
    __syncthreads();
    float avg = rsm * (1.0f / 1024.0f);
    float scale = EPSDS * (rmx - rmn);

    float r0[4], r1[4], r2[4];
#pragma unroll
    for (int j = 0; j < 4; j++) {
        float t = (mvn[j] - avg) / scale;
        float r = 1.0f / (1.0f + expf(t));
        if (r != r) r = 1.0f;
        r0[j] = mean[j] * has;
        r1[j] = (wr[j] + LRC * (mean[j] - wr[j])) * has;
        r2[j] = r * has;
    }
    ((float4*)(out0 + (size_t)n * DD))[tid] = make_float4(r0[0], r0[1], r0[2], r0[3]);
    ((float4*)(out1 + (size_t)n * DD))[tid] = make_float4(r1[0], r1[1], r1[2], r1[3]);
    ((float4*)(out2 + (size_t)n * DD))[tid] = make_float4(r2[0], r2[1], r2[2], r2[3]);
}

// ---------------------------------------------------------------------------
extern "C" void kernel_launch(void* const* d_in, const int* in_sizes, int n_in,
                              void* d_out, int out_size) {
    const float* x    = (const float*)d_in[0];
    const float* wts  = (const float*)d_in[1];
    const float* rel  = (const float*)d_in[2];
    const float* mavg = (const float*)d_in[3];
    const float* nc   = (const float*)d_in[4];
    float* out = (float*)d_out;

    cudaFuncSetAttribute(k_gemm_bf16, cudaFuncAttributeMaxDynamicSharedMemorySize, GEMM_SMEM);

    k_init<<<(NN * DD / 4) / 256, 256>>>((float4*)out);
    k_rowprep<<<BB + NN, 256>>>(x, wts, rel);
    dim3 g(NN / 128, BB / 128);
    k_gemm_bf16<<<g, 256, GEMM_SMEM>>>(nc);
    k_argmax<<<BB, 256>>>(x, wts, nc);
    k_scatter<<<BB, 256>>>(x, out);
    k_final<<<NN, 256>>>(wts, mavg, out);
}